// round 1
// baseline (speedup 1.0000x reference)
#include <cuda_runtime.h>
#include <cstdint>

// Problem constants (from reference)
#define B     64
#define N_SV  63
#define HID   512
#define NEW_W 28
#define NEW_H 28
// xIdx = int(x * 28/224) = int(x / 8)
#define POS_DIV 8.0f

// ---------------------------------------------------------------------------
// Kernel 1: zero-fill the output grid. 102.8 MB of fp32 -> float4 stores.
// out_size = B*HID*NEW_W*NEW_H = 25,690,112 floats = 6,422,528 float4.
// ---------------------------------------------------------------------------
__global__ void zero_kernel(float4* __restrict__ out, int n4) {
    int i = blockIdx.x * blockDim.x + threadIdx.x;
    int stride = gridDim.x * blockDim.x;
    float4 z = make_float4(0.f, 0.f, 0.f, 0.f);
    for (; i < n4; i += stride) out[i] = z;
}

// ---------------------------------------------------------------------------
// Kernel 2: scatter-max. One block per (b, agent). 128 threads, each thread
// handles 4 consecutive hid channels via a float4 load of the encoding row.
// All final grid values are >= 0 (max with zero-init), so atomicMax on
// int-reinterpreted non-negative floats is exact. Non-positive encoding
// values are skipped (they cannot beat the 0 init).
// ---------------------------------------------------------------------------
__global__ void scatter_kernel(const float* __restrict__ pos,   // (B, N_SV, 3)
                               const float4* __restrict__ enc,  // (B, N_SV, HID) as float4
                               const int* __restrict__ lengths, // (B,)
                               int* __restrict__ out_i)         // grid as int bits
{
    const int b = blockIdx.x;   // 0..B-1
    const int a = blockIdx.y;   // 0..N_SV-1

    // Validity: agent index < lengths[b], and projected cell inside grid.
    if (a >= lengths[b]) return;

    const float x = pos[(b * N_SV + a) * 3 + 0];
    const float y = pos[(b * N_SV + a) * 3 + 1];
    const int xIdx = (int)(x * ((float)NEW_W / 224.0f));  // trunc toward zero
    const int yIdx = (int)(y * ((float)NEW_H / 224.0f));
    if (xIdx >= NEW_W || yIdx >= NEW_H) return;

    // Clamp (positions are positive in practice; clamp matches reference clip)
    const int xI = xIdx < 0 ? 0 : xIdx;
    const int yI = yIdx < 0 ? 0 : yIdx;

    // Base of grid[b, 0, xI, yI]; channel stride = NEW_W*NEW_H = 784.
    int* base = out_i + ((size_t)b * HID * NEW_W * NEW_H) + (size_t)xI * NEW_H + yI;

    const int t = threadIdx.x;          // 0..127, each covers 4 channels
    const float4 v = enc[((size_t)b * N_SV + a) * (HID / 4) + t];
    const int h0 = t * 4;

    if (v.x > 0.f) atomicMax(base + (size_t)(h0 + 0) * (NEW_W * NEW_H), __float_as_int(v.x));
    if (v.y > 0.f) atomicMax(base + (size_t)(h0 + 1) * (NEW_W * NEW_H), __float_as_int(v.y));
    if (v.z > 0.f) atomicMax(base + (size_t)(h0 + 2) * (NEW_W * NEW_H), __float_as_int(v.z));
    if (v.w > 0.f) atomicMax(base + (size_t)(h0 + 3) * (NEW_W * NEW_H), __float_as_int(v.w));
}

extern "C" void kernel_launch(void* const* d_in, const int* in_sizes, int n_in,
                              void* d_out, int out_size) {
    const float* pos     = (const float*)d_in[0];   // (B, N_SV, 3)
    const float* enc     = (const float*)d_in[1];   // (B, N_SV, HID)
    const int*   lengths = (const int*)d_in[2];     // (B,)

    // 1) zero-fill the grid
    int n4 = out_size / 4;                          // 6,422,528 float4
    int threads = 256;
    int blocks = (n4 + threads * 4 - 1) / (threads * 4); // grid-stride, ~4 iters/thread
    if (blocks > 25088) blocks = 25088;
    zero_kernel<<<blocks, threads>>>((float4*)d_out, n4);

    // 2) scatter-max the valid agents
    dim3 grid(B, N_SV);
    scatter_kernel<<<grid, HID / 4>>>(pos, (const float4*)enc, lengths, (int*)d_out);
}